// round 1
// baseline (speedup 1.0000x reference)
#include <cuda_runtime.h>

#define N_TOT 2097152
#define MASK  (N_TOT - 1)
#define TILE  256
#define NT    256

// ---------------- shared memory layout (float offsets) ----------------
// activation rows padded to stride 264 (coprime-ish with banks, float4 safe)
#define XS 264
constexpr int S_DIF = 0;                    // 266 used (TILE+10)
constexpr int S_X1  = 272;                  // 20 x 264   (TILE+6 valid)
constexpr int S_X2  = S_X1 + 20 * XS;       // 40 x 264   (TILE+2 valid)
constexpr int S_X4  = S_X2 + 40 * XS;       // 40 x 264   (TILE+2 valid)
constexpr int S_W1  = S_X4 + 40 * XS;       // [k5][co20]
constexpr int S_B1  = S_W1 + 100;
constexpr int S_W2  = S_B1 + 20;            // [ci20][k5][co40]
constexpr int S_B2  = S_W2 + 4000;
constexpr int S_W3  = S_B2 + 40;            // [ci40][co80]
constexpr int S_B3  = S_W3 + 3200;
constexpr int S_W4  = S_B3 + 80;            // [ci80][co40]
constexpr int S_B4  = S_W4 + 3200;
constexpr int S_W5  = S_B4 + 40;            // [ci40][k3][co20]
constexpr int S_B5  = S_W5 + 2400;
constexpr int S_W6  = S_B5 + 20;            // [ci20]
constexpr int S_B6  = S_W6 + 20;
constexpr int S_TOTF = S_B6 + 4;
constexpr int SMEM_BYTES = S_TOTF * 4;      // ~159 KB

__device__ float g_bm[N_TOT];

__device__ __forceinline__ float elu_f(float x) {
    return x > 0.0f ? x : (__expf(x) - 1.0f);
}

// =====================================================================
// Kernel A: CNN  ->  g_bm = sigmoid(cnn(dif)) + 0.1
// =====================================================================
__global__ __launch_bounds__(NT, 1)
void cnn_kernel(const float* __restrict__ uu,
                const float* __restrict__ w1, const float* __restrict__ b1,
                const float* __restrict__ w2, const float* __restrict__ b2,
                const float* __restrict__ w3, const float* __restrict__ b3,
                const float* __restrict__ w4, const float* __restrict__ b4,
                const float* __restrict__ w5, const float* __restrict__ b5,
                const float* __restrict__ w6, const float* __restrict__ b6)
{
    extern __shared__ float s[];
    const int tid  = threadIdx.x;
    const int base = blockIdx.x * TILE;

    // ---------------- stage weights into smem (transposed: co innermost)
    for (int i = tid; i < 100; i += NT) {              // w1 (20,1,5)
        int co = i / 5, k = i % 5;
        s[S_W1 + k * 20 + co] = w1[i];
    }
    for (int i = tid; i < 20; i += NT) s[S_B1 + i] = b1[i];
    for (int i = tid; i < 4000; i += NT) {             // w2 (40,20,5)
        int co = i / 100, r = i % 100, ci = r / 5, k = r % 5;
        s[S_W2 + (ci * 5 + k) * 40 + co] = w2[i];
    }
    for (int i = tid; i < 40; i += NT) s[S_B2 + i] = b2[i];
    for (int i = tid; i < 3200; i += NT) {             // w3 (80,40,1)
        int co = i / 40, ci = i % 40;
        s[S_W3 + ci * 80 + co] = w3[i];
    }
    for (int i = tid; i < 80; i += NT) s[S_B3 + i] = b3[i];
    for (int i = tid; i < 3200; i += NT) {             // w4 (40,80,1)
        int co = i / 80, ci = i % 80;
        s[S_W4 + ci * 40 + co] = w4[i];
    }
    for (int i = tid; i < 40; i += NT) s[S_B4 + i] = b4[i];
    for (int i = tid; i < 2400; i += NT) {             // w5 (20,40,3)
        int co = i / 120, r = i % 120, ci = r / 3, k = r % 3;
        s[S_W5 + (ci * 3 + k) * 20 + co] = w5[i];
    }
    for (int i = tid; i < 20; i += NT) s[S_B5 + i] = b5[i];
    for (int i = tid; i < 20; i += NT) s[S_W6 + i] = w6[i];
    if (tid == 0) s[S_B6] = b6[0];

    // ---------------- stage A: dif at [base-5, base+TILE+5)
    for (int j = tid; j < TILE + 10; j += NT) {
        int g = base - 5 + j;
        float v = 0.0f;
        if (g >= 0 && g < N_TOT) {
            if (g == 0)              v = uu[1] - uu[0];
            else if (g == N_TOT - 1) v = uu[N_TOT - 1] - uu[N_TOT - 2];
            else                     v = 0.5f * (uu[g + 1] - uu[g - 1]);
        }
        s[S_DIF + j] = v;
    }
    __syncthreads();

    // ---------------- stage B: conv1(1->20,k5,p2)+elu at [base-3, base+TILE+3)
    for (int pj = tid; pj < TILE + 6; pj += NT) {
        int g = base - 3 + pj;
        if (g < 0 || g >= N_TOT) {
            #pragma unroll
            for (int co = 0; co < 20; co++) s[S_X1 + co * XS + pj] = 0.0f;
        } else {
            float a[20];
            #pragma unroll
            for (int co = 0; co < 20; co++) a[co] = s[S_B1 + co];
            #pragma unroll
            for (int k = 0; k < 5; k++) {
                float dv = s[S_DIF + pj + k];
                #pragma unroll
                for (int co = 0; co < 20; co++)
                    a[co] = fmaf(dv, s[S_W1 + k * 20 + co], a[co]);
            }
            #pragma unroll
            for (int co = 0; co < 20; co++)
                s[S_X1 + co * XS + pj] = elu_f(a[co]);
        }
    }
    __syncthreads();

    // ---------------- stage C: conv2(20->40,k5,p2)+elu at [base-1, base+TILE+1)
    for (int pi = tid; pi < TILE + 2; pi += NT) {
        int g = base - 1 + pi;
        if (g < 0 || g >= N_TOT) {
            #pragma unroll
            for (int co = 0; co < 40; co++) s[S_X2 + co * XS + pi] = 0.0f;
        } else {
            float a[40];
            #pragma unroll
            for (int co = 0; co < 40; co++) a[co] = s[S_B2 + co];
            int ap = S_X1 + pi;
            for (int ci = 0; ci < 20; ci++) {
                int wb = S_W2 + ci * 200;
                #pragma unroll
                for (int k = 0; k < 5; k++) {
                    float v = s[ap + k];
                    #pragma unroll
                    for (int cg = 0; cg < 40; cg += 4) {
                        float4 w = *(const float4*)&s[wb + k * 40 + cg];
                        a[cg + 0] = fmaf(v, w.x, a[cg + 0]);
                        a[cg + 1] = fmaf(v, w.y, a[cg + 1]);
                        a[cg + 2] = fmaf(v, w.z, a[cg + 2]);
                        a[cg + 3] = fmaf(v, w.w, a[cg + 3]);
                    }
                }
                ap += XS;
            }
            #pragma unroll
            for (int co = 0; co < 40; co++)
                s[S_X2 + co * XS + pi] = elu_f(a[co]);
        }
    }
    __syncthreads();

    // ---------------- stage D: conv3(40->80,1x1)+elu, conv4(80->40,1x1)+elu
    for (int pi = tid; pi < TILE + 2; pi += NT) {
        int g = base - 1 + pi;
        if (g < 0 || g >= N_TOT) {
            #pragma unroll
            for (int co = 0; co < 40; co++) s[S_X4 + co * XS + pi] = 0.0f;
        } else {
            float x3[80];
            #pragma unroll
            for (int co = 0; co < 80; co++) x3[co] = s[S_B3 + co];
            for (int ci = 0; ci < 40; ci++) {
                float v = s[S_X2 + ci * XS + pi];
                #pragma unroll
                for (int cg = 0; cg < 80; cg += 4) {
                    float4 w = *(const float4*)&s[S_W3 + ci * 80 + cg];
                    x3[cg + 0] = fmaf(v, w.x, x3[cg + 0]);
                    x3[cg + 1] = fmaf(v, w.y, x3[cg + 1]);
                    x3[cg + 2] = fmaf(v, w.z, x3[cg + 2]);
                    x3[cg + 3] = fmaf(v, w.w, x3[cg + 3]);
                }
            }
            float a4[40];
            #pragma unroll
            for (int co = 0; co < 40; co++) a4[co] = s[S_B4 + co];
            #pragma unroll
            for (int ci = 0; ci < 80; ci++) {
                float v = elu_f(x3[ci]);
                #pragma unroll
                for (int cg = 0; cg < 40; cg += 4) {
                    float4 w = *(const float4*)&s[S_W4 + ci * 40 + cg];
                    a4[cg + 0] = fmaf(v, w.x, a4[cg + 0]);
                    a4[cg + 1] = fmaf(v, w.y, a4[cg + 1]);
                    a4[cg + 2] = fmaf(v, w.z, a4[cg + 2]);
                    a4[cg + 3] = fmaf(v, w.w, a4[cg + 3]);
                }
            }
            #pragma unroll
            for (int co = 0; co < 40; co++)
                s[S_X4 + co * XS + pi] = elu_f(a4[co]);
        }
    }
    __syncthreads();

    // ---------------- stage E: conv5(40->20,k3,p1)+elu, conv6(20->1)+sigmoid
    for (int pe = tid; pe < TILE; pe += NT) {
        float a[20];
        #pragma unroll
        for (int co = 0; co < 20; co++) a[co] = s[S_B5 + co];
        for (int ci = 0; ci < 40; ci++) {
            #pragma unroll
            for (int k = 0; k < 3; k++) {
                float v = s[S_X4 + ci * XS + pe + k];
                #pragma unroll
                for (int cg = 0; cg < 20; cg += 4) {
                    float4 w = *(const float4*)&s[S_W5 + (ci * 3 + k) * 20 + cg];
                    a[cg + 0] = fmaf(v, w.x, a[cg + 0]);
                    a[cg + 1] = fmaf(v, w.y, a[cg + 1]);
                    a[cg + 2] = fmaf(v, w.z, a[cg + 2]);
                    a[cg + 3] = fmaf(v, w.w, a[cg + 3]);
                }
            }
        }
        float bmacc = s[S_B6];
        #pragma unroll
        for (int co = 0; co < 20; co++)
            bmacc = fmaf(elu_f(a[co]), s[S_W6 + co], bmacc);
        float sig = 1.0f / (1.0f + __expf(-bmacc));
        g_bm[base + pe] = sig + 0.1f;
    }
}

// =====================================================================
// Kernel B: WENO5 (periodic)
// =====================================================================
__device__ __forceinline__ void omegas3(float b0, float b1, float b2,
                                        float& o0, float& o1, float& o2)
{
    const float E = 1e-13f;
    float brs = (b2 - b0); brs *= brs;
    float t0 = E + b0; t0 *= t0;
    float t1 = E + b1; t1 *= t1;
    float t2 = E + b2; t2 *= t2;
    float m0 = 0.1f * (brs / t0 + 1.0f);
    float m1 = 0.6f * (brs / t1 + 1.0f);
    float m2 = 0.3f * (brs / t2 + 1.0f);
    float inv = 1.0f / (m0 + m1 + m2);
    o0 = m0 * inv; o1 = m1 * inv; o2 = m2 * inv;
}

__global__ __launch_bounds__(256)
void weno_kernel(const float* __restrict__ uu, float* __restrict__ out)
{
    int i = blockIdx.x * 256 + threadIdx.x;

    float um2 = uu[(i - 2) & MASK];
    float um1 = uu[(i - 1) & MASK];
    float u0  = uu[i];
    float up1 = uu[(i + 1) & MASK];
    float up2 = uu[(i + 2) & MASK];
    float up3 = uu[(i + 3) & MASK];

    float bmm = g_bm[(i - 1) & MASK];
    float bm0 = g_bm[i];
    float bmp = g_bm[(i + 1) & MASK];

    const float c16 = 1.0f / 6.0f;
    const float c1312 = 13.0f / 12.0f;

    // fluxes(uu) centered at i
    float fn0 = (11.0f * u0 - 7.0f * up1 + 2.0f * up2) * c16;
    float fn1 = (2.0f * um1 + 5.0f * u0 - up1) * c16;
    float fn2 = (-um2 + 5.0f * um1 + 2.0f * u0) * c16;
    // fluxes(roll(uu,-1)) centered at i  (shift all indices +1)
    float fp0 = (11.0f * up1 - 7.0f * up2 + 2.0f * up3) * c16;
    float fp1 = (2.0f * u0 + 5.0f * up1 - up2) * c16;
    float fp2 = (-um1 + 5.0f * u0 + 2.0f * up1) * c16;

    // betas(uu)
    float t;
    t = u0 - 2.0f * up1 + up2;
    float bn0 = c1312 * t * t;
    t = 3.0f * u0 - 4.0f * up1 + up2;
    bn0 += 0.25f * t * t;
    t = um1 - 2.0f * u0 + up1;
    float bn1 = c1312 * t * t;
    t = um1 - up1;
    bn1 += 0.25f * t * t;
    t = um2 - 2.0f * um1 + u0;
    float bn2 = c1312 * t * t;
    t = um2 - 4.0f * um1 + 3.0f * u0;
    bn2 += 0.25f * t * t;

    // betas(roll(uu,-1))
    t = up1 - 2.0f * up2 + up3;
    float bp0 = c1312 * t * t;
    t = 3.0f * up1 - 4.0f * up2 + up3;
    bp0 += 0.25f * t * t;
    t = u0 - 2.0f * up1 + up2;
    float bp1 = c1312 * t * t;
    t = u0 - up2;
    bp1 += 0.25f * t * t;
    t = um1 - 2.0f * u0 + up1;
    float bp2 = c1312 * t * t;
    t = um1 - 4.0f * u0 + 3.0f * up1;
    bp2 += 0.25f * t * t;

    // modulate by bm: b_k *= roll(bm, k-1)  ->  k=0: bm[i+1], k=1: bm[i], k=2: bm[i-1]
    bn0 *= bmp; bn1 *= bm0; bn2 *= bmm;
    bp0 *= bmp; bp1 *= bm0; bp2 *= bmm;

    float on0, on1, on2, op0, op1, op2;
    omegas3(bn0, bn1, bn2, on0, on1, on2);
    omegas3(bp0, bp1, bp2, op0, op1, op2);

    float fluxp = op0 * fp0 + op1 * fp1 + op2 * fp2;
    float fluxn = on0 * fn0 + on1 * fn1 + on2 * fn2;
    out[i] = fluxp - fluxn;
}

// =====================================================================
extern "C" void kernel_launch(void* const* d_in, const int* in_sizes, int n_in,
                              void* d_out, int out_size)
{
    (void)in_sizes; (void)n_in; (void)out_size;
    const float* uu = (const float*)d_in[0];
    const float* w1 = (const float*)d_in[1];  const float* b1 = (const float*)d_in[2];
    const float* w2 = (const float*)d_in[3];  const float* b2 = (const float*)d_in[4];
    const float* w3 = (const float*)d_in[5];  const float* b3 = (const float*)d_in[6];
    const float* w4 = (const float*)d_in[7];  const float* b4 = (const float*)d_in[8];
    const float* w5 = (const float*)d_in[9];  const float* b5 = (const float*)d_in[10];
    const float* w6 = (const float*)d_in[11]; const float* b6 = (const float*)d_in[12];

    cudaFuncSetAttribute(cnn_kernel,
                         cudaFuncAttributeMaxDynamicSharedMemorySize, SMEM_BYTES);

    cnn_kernel<<<N_TOT / TILE, NT, SMEM_BYTES>>>(uu, w1, b1, w2, b2, w3, b3,
                                                 w4, b4, w5, b5, w6, b6);
    weno_kernel<<<N_TOT / 256, 256>>>(uu, (float*)d_out);
}

// round 2
// speedup vs baseline: 1.2707x; 1.2707x over previous
#include <cuda_runtime.h>

#define N_TOT 2097152
#define MASK  (N_TOT - 1)
#define TILE  512
#define NT    256

typedef unsigned long long u64;

// ---------------- shared memory layout (float offsets) ----------------
#define XS 520   // row stride for activation arrays (even, >= 518)
constexpr int S_DIF = 0;                    // 522 used, pad to 528
constexpr int S_XA  = 528;                  // union: X1 rows 0-19 (stages B,C), X4 rows 0-39 (stages D,E)
constexpr int S_XB  = S_XA + 40 * XS;       // X2: 40 rows
constexpr int S_W1  = S_XB + 40 * XS;       // [k5][co20]
constexpr int S_B1  = S_W1 + 100;
constexpr int S_W2  = S_B1 + 20;            // [ci20][k5][co40]
constexpr int S_B2  = S_W2 + 4000;
constexpr int S_W3  = S_B2 + 40;            // [ci40][co80]
constexpr int S_B3  = S_W3 + 3200;
constexpr int S_W4  = S_B3 + 80;            // [ci80][co40]
constexpr int S_B4  = S_W4 + 3200;
constexpr int S_W5  = S_B4 + 40;            // [ci40][k3][co20]
constexpr int S_B5  = S_W5 + 2400;
constexpr int S_W6  = S_B5 + 20;            // [ci20]
constexpr int S_B6  = S_W6 + 20;
constexpr int S_TOTF = S_B6 + 4;
constexpr int SMEM_BYTES = S_TOTF * 4;      // 221,008 B <= 227 KB

__device__ float g_bm[N_TOT];

__device__ __forceinline__ float elu_f(float x) {
    return x > 0.0f ? x : (__expf(x) - 1.0f);
}

// ---- packed f32x2 helpers ----
__device__ __forceinline__ u64 f2fma(u64 a, u64 b, u64 c) {
    u64 d;
    asm("fma.rn.f32x2 %0, %1, %2, %3;" : "=l"(d) : "l"(a), "l"(b), "l"(c));
    return d;
}
__device__ __forceinline__ u64 f2pack(float lo, float hi) {
    u64 d; asm("mov.b64 %0, {%1, %2};" : "=l"(d) : "f"(lo), "f"(hi)); return d;
}
__device__ __forceinline__ u64 f2splat(float v) {
    u64 d; asm("mov.b64 %0, {%1, %1};" : "=l"(d) : "f"(v)); return d;
}
__device__ __forceinline__ void f2unpack(u64 v, float& lo, float& hi) {
    asm("mov.b64 {%0, %1}, %2;" : "=f"(lo), "=f"(hi) : "l"(v));
}

// =====================================================================
// Kernel A: CNN  ->  g_bm = sigmoid(cnn(dif)) + 0.1
// Each thread computes 2 adjacent positions; channels packed 2/reg (f32x2).
// =====================================================================
__global__ __launch_bounds__(NT, 1)
void cnn_kernel(const float* __restrict__ uu,
                const float* __restrict__ w1, const float* __restrict__ b1,
                const float* __restrict__ w2, const float* __restrict__ b2,
                const float* __restrict__ w3, const float* __restrict__ b3,
                const float* __restrict__ w4, const float* __restrict__ b4,
                const float* __restrict__ w5, const float* __restrict__ b5,
                const float* __restrict__ w6, const float* __restrict__ b6)
{
    extern __shared__ float s[];
    const int tid  = threadIdx.x;
    const int base = blockIdx.x * TILE;

    // ---------------- stage weights into smem (co innermost)
    for (int i = tid; i < 100; i += NT) {              // w1 (20,1,5)
        int co = i / 5, k = i % 5;
        s[S_W1 + k * 20 + co] = w1[i];
    }
    for (int i = tid; i < 20; i += NT) s[S_B1 + i] = b1[i];
    for (int i = tid; i < 4000; i += NT) {             // w2 (40,20,5)
        int co = i / 100, r = i % 100, ci = r / 5, k = r % 5;
        s[S_W2 + (ci * 5 + k) * 40 + co] = w2[i];
    }
    for (int i = tid; i < 40; i += NT) s[S_B2 + i] = b2[i];
    for (int i = tid; i < 3200; i += NT) {             // w3 (80,40,1)
        int co = i / 40, ci = i % 40;
        s[S_W3 + ci * 80 + co] = w3[i];
    }
    for (int i = tid; i < 80; i += NT) s[S_B3 + i] = b3[i];
    for (int i = tid; i < 3200; i += NT) {             // w4 (40,80,1)
        int co = i / 80, ci = i % 80;
        s[S_W4 + ci * 40 + co] = w4[i];
    }
    for (int i = tid; i < 40; i += NT) s[S_B4 + i] = b4[i];
    for (int i = tid; i < 2400; i += NT) {             // w5 (20,40,3)
        int co = i / 120, r = i % 120, ci = r / 3, k = r % 3;
        s[S_W5 + (ci * 3 + k) * 20 + co] = w5[i];
    }
    for (int i = tid; i < 20; i += NT) s[S_B5 + i] = b5[i];
    for (int i = tid; i < 20; i += NT) s[S_W6 + i] = w6[i];
    if (tid == 0) s[S_B6] = b6[0];

    // ---------------- stage A: dif at [base-5, base+TILE+5)
    for (int j = tid; j < TILE + 10; j += NT) {
        int g = base - 5 + j;
        float v = 0.0f;
        if (g >= 0 && g < N_TOT) {
            if (g == 0)              v = uu[1] - uu[0];
            else if (g == N_TOT - 1) v = uu[N_TOT - 1] - uu[N_TOT - 2];
            else                     v = 0.5f * (uu[g + 1] - uu[g - 1]);
        }
        s[S_DIF + j] = v;
    }
    __syncthreads();

    // ---------------- stage B: conv1(1->20,k5,p2)+elu at X1[0, TILE+6)
    for (int pj = 2 * tid; pj < TILE + 6; pj += 2 * NT) {
        int g0 = base - 3 + pj;
        u64 a0[10], a1[10];
        #pragma unroll
        for (int cp = 0; cp < 10; cp++) {
            u64 b = *(const u64*)&s[S_B1 + 2 * cp];
            a0[cp] = b; a1[cp] = b;
        }
        #pragma unroll
        for (int k = 0; k < 5; k++) {
            u64 vv0 = f2splat(s[S_DIF + pj + k]);
            u64 vv1 = f2splat(s[S_DIF + pj + k + 1]);
            const ulonglong2* wp = (const ulonglong2*)&s[S_W1 + k * 20];
            #pragma unroll
            for (int q = 0; q < 5; q++) {
                ulonglong2 w = wp[q];
                a0[2*q]   = f2fma(vv0, w.x, a0[2*q]);
                a1[2*q]   = f2fma(vv1, w.x, a1[2*q]);
                a0[2*q+1] = f2fma(vv0, w.y, a0[2*q+1]);
                a1[2*q+1] = f2fma(vv1, w.y, a1[2*q+1]);
            }
        }
        bool v0 = (g0 >= 0 && g0 < N_TOT);
        bool v1 = (g0 + 1 >= 0 && g0 + 1 < N_TOT);
        #pragma unroll
        for (int cp = 0; cp < 10; cp++) {
            float x00, x01, x10, x11;
            f2unpack(a0[cp], x00, x01);   // (co=2cp, co=2cp+1) at pos0
            f2unpack(a1[cp], x10, x11);   // at pos1
            float e00 = v0 ? elu_f(x00) : 0.0f;
            float e01 = v0 ? elu_f(x01) : 0.0f;
            float e10 = v1 ? elu_f(x10) : 0.0f;
            float e11 = v1 ? elu_f(x11) : 0.0f;
            *(u64*)&s[S_XA + (2*cp)     * XS + pj] = f2pack(e00, e10);
            *(u64*)&s[S_XA + (2*cp + 1) * XS + pj] = f2pack(e01, e11);
        }
    }
    __syncthreads();

    // ---------------- stage C: conv2(20->40,k5,p2)+elu at X2[0, TILE+2)
    for (int pi = 2 * tid; pi < TILE + 2; pi += 2 * NT) {
        int g0 = base - 1 + pi;
        u64 acc0[20], acc1[20];
        #pragma unroll
        for (int cp = 0; cp < 20; cp++) {
            u64 b = *(const u64*)&s[S_B2 + 2 * cp];
            acc0[cp] = b; acc1[cp] = b;
        }
        #pragma unroll 1
        for (int ci = 0; ci < 20; ci++) {
            const float* xr = &s[S_XA + ci * XS + pi];
            #pragma unroll
            for (int k = 0; k < 5; k++) {
                u64 vv0 = f2splat(xr[k]);
                u64 vv1 = f2splat(xr[k + 1]);
                const ulonglong2* wp = (const ulonglong2*)&s[S_W2 + (ci * 5 + k) * 40];
                #pragma unroll
                for (int q = 0; q < 10; q++) {
                    ulonglong2 w = wp[q];
                    acc0[2*q]   = f2fma(vv0, w.x, acc0[2*q]);
                    acc1[2*q]   = f2fma(vv1, w.x, acc1[2*q]);
                    acc0[2*q+1] = f2fma(vv0, w.y, acc0[2*q+1]);
                    acc1[2*q+1] = f2fma(vv1, w.y, acc1[2*q+1]);
                }
            }
        }
        bool v0 = (g0 >= 0 && g0 < N_TOT);
        bool v1 = (g0 + 1 >= 0 && g0 + 1 < N_TOT);
        #pragma unroll
        for (int cp = 0; cp < 20; cp++) {
            float x00, x01, x10, x11;
            f2unpack(acc0[cp], x00, x01);
            f2unpack(acc1[cp], x10, x11);
            float e00 = v0 ? elu_f(x00) : 0.0f;
            float e01 = v0 ? elu_f(x01) : 0.0f;
            float e10 = v1 ? elu_f(x10) : 0.0f;
            float e11 = v1 ? elu_f(x11) : 0.0f;
            *(u64*)&s[S_XB + (2*cp)     * XS + pi] = f2pack(e00, e10);
            *(u64*)&s[S_XB + (2*cp + 1) * XS + pi] = f2pack(e01, e11);
        }
    }
    __syncthreads();

    // ---------------- stage D: conv3(40->80,1x1)+elu, conv4(80->40,1x1)+elu
    // x3 computed in 4 chunks of 20 channels to bound registers.
    for (int pi = 2 * tid; pi < TILE + 2; pi += 2 * NT) {
        int g0 = base - 1 + pi;
        u64 a4_0[20], a4_1[20];
        #pragma unroll
        for (int cp = 0; cp < 20; cp++) {
            u64 b = *(const u64*)&s[S_B4 + 2 * cp];
            a4_0[cp] = b; a4_1[cp] = b;
        }
        #pragma unroll 1
        for (int ch = 0; ch < 4; ch++) {
            u64 x0[10], x1p[10];
            #pragma unroll
            for (int cp = 0; cp < 10; cp++) {
                u64 b = *(const u64*)&s[S_B3 + 20 * ch + 2 * cp];
                x0[cp] = b; x1p[cp] = b;
            }
            #pragma unroll 1
            for (int ci = 0; ci < 40; ci++) {
                float v0s, v1s;
                f2unpack(*(const u64*)&s[S_XB + ci * XS + pi], v0s, v1s);
                u64 vv0 = f2splat(v0s);
                u64 vv1 = f2splat(v1s);
                const ulonglong2* wp = (const ulonglong2*)&s[S_W3 + ci * 80 + 20 * ch];
                #pragma unroll
                for (int q = 0; q < 5; q++) {
                    ulonglong2 w = wp[q];
                    x0[2*q]    = f2fma(vv0, w.x, x0[2*q]);
                    x1p[2*q]   = f2fma(vv1, w.x, x1p[2*q]);
                    x0[2*q+1]  = f2fma(vv0, w.y, x0[2*q+1]);
                    x1p[2*q+1] = f2fma(vv1, w.y, x1p[2*q+1]);
                }
            }
            // elu(x3 chunk) then accumulate conv4
            #pragma unroll
            for (int j = 0; j < 10; j++) {
                float p00, p01, p10, p11;
                f2unpack(x0[j],  p00, p01);   // channels 20ch+2j, +2j+1 at pos0
                f2unpack(x1p[j], p10, p11);   // at pos1
                float e00 = elu_f(p00), e01 = elu_f(p01);
                float e10 = elu_f(p10), e11 = elu_f(p11);
                {
                    u64 vv0 = f2splat(e00), vv1 = f2splat(e10);
                    const ulonglong2* wp = (const ulonglong2*)&s[S_W4 + (20*ch + 2*j) * 40];
                    #pragma unroll
                    for (int q = 0; q < 10; q++) {
                        ulonglong2 w = wp[q];
                        a4_0[2*q]   = f2fma(vv0, w.x, a4_0[2*q]);
                        a4_1[2*q]   = f2fma(vv1, w.x, a4_1[2*q]);
                        a4_0[2*q+1] = f2fma(vv0, w.y, a4_0[2*q+1]);
                        a4_1[2*q+1] = f2fma(vv1, w.y, a4_1[2*q+1]);
                    }
                }
                {
                    u64 vv0 = f2splat(e01), vv1 = f2splat(e11);
                    const ulonglong2* wp = (const ulonglong2*)&s[S_W4 + (20*ch + 2*j + 1) * 40];
                    #pragma unroll
                    for (int q = 0; q < 10; q++) {
                        ulonglong2 w = wp[q];
                        a4_0[2*q]   = f2fma(vv0, w.x, a4_0[2*q]);
                        a4_1[2*q]   = f2fma(vv1, w.x, a4_1[2*q]);
                        a4_0[2*q+1] = f2fma(vv0, w.y, a4_0[2*q+1]);
                        a4_1[2*q+1] = f2fma(vv1, w.y, a4_1[2*q+1]);
                    }
                }
            }
        }
        bool v0 = (g0 >= 0 && g0 < N_TOT);
        bool v1 = (g0 + 1 >= 0 && g0 + 1 < N_TOT);
        #pragma unroll
        for (int cp = 0; cp < 20; cp++) {
            float x00, x01, x10, x11;
            f2unpack(a4_0[cp], x00, x01);
            f2unpack(a4_1[cp], x10, x11);
            float e00 = v0 ? elu_f(x00) : 0.0f;
            float e01 = v0 ? elu_f(x01) : 0.0f;
            float e10 = v1 ? elu_f(x10) : 0.0f;
            float e11 = v1 ? elu_f(x11) : 0.0f;
            *(u64*)&s[S_XA + (2*cp)     * XS + pi] = f2pack(e00, e10);
            *(u64*)&s[S_XA + (2*cp + 1) * XS + pi] = f2pack(e01, e11);
        }
    }
    __syncthreads();

    // ---------------- stage E: conv5(40->20,k3,p1)+elu, conv6(20->1)+sigmoid
    {
        const int pe = 2 * tid;             // TILE == 2*NT: one pair per thread
        u64 a0[10], a1[10];
        #pragma unroll
        for (int cp = 0; cp < 10; cp++) {
            u64 b = *(const u64*)&s[S_B5 + 2 * cp];
            a0[cp] = b; a1[cp] = b;
        }
        #pragma unroll 1
        for (int ci = 0; ci < 40; ci++) {
            const float* xr = &s[S_XA + ci * XS + pe];
            #pragma unroll
            for (int k = 0; k < 3; k++) {
                u64 vv0 = f2splat(xr[k]);
                u64 vv1 = f2splat(xr[k + 1]);
                const ulonglong2* wp = (const ulonglong2*)&s[S_W5 + (ci * 3 + k) * 20];
                #pragma unroll
                for (int q = 0; q < 5; q++) {
                    ulonglong2 w = wp[q];
                    a0[2*q]   = f2fma(vv0, w.x, a0[2*q]);
                    a1[2*q]   = f2fma(vv1, w.x, a1[2*q]);
                    a0[2*q+1] = f2fma(vv0, w.y, a0[2*q+1]);
                    a1[2*q+1] = f2fma(vv1, w.y, a1[2*q+1]);
                }
            }
        }
        float s0 = s[S_B6], s1 = s[S_B6];
        #pragma unroll
        for (int cp = 0; cp < 10; cp++) {
            float x00, x01, x10, x11;
            f2unpack(a0[cp], x00, x01);
            f2unpack(a1[cp], x10, x11);
            float wA = s[S_W6 + 2 * cp], wB = s[S_W6 + 2 * cp + 1];
            s0 = fmaf(elu_f(x00), wA, s0);
            s0 = fmaf(elu_f(x01), wB, s0);
            s1 = fmaf(elu_f(x10), wA, s1);
            s1 = fmaf(elu_f(x11), wB, s1);
        }
        float r0 = 1.0f / (1.0f + __expf(-s0)) + 0.1f;
        float r1 = 1.0f / (1.0f + __expf(-s1)) + 0.1f;
        *(u64*)&g_bm[base + pe] = f2pack(r0, r1);
    }
}

// =====================================================================
// Kernel B: WENO5 (periodic)
// =====================================================================
__device__ __forceinline__ void omegas3(float b0, float b1, float b2,
                                        float& o0, float& o1, float& o2)
{
    const float E = 1e-13f;
    float brs = (b2 - b0); brs *= brs;
    float t0 = E + b0; t0 *= t0;
    float t1 = E + b1; t1 *= t1;
    float t2 = E + b2; t2 *= t2;
    float m0 = 0.1f * (brs / t0 + 1.0f);
    float m1 = 0.6f * (brs / t1 + 1.0f);
    float m2 = 0.3f * (brs / t2 + 1.0f);
    float inv = 1.0f / (m0 + m1 + m2);
    o0 = m0 * inv; o1 = m1 * inv; o2 = m2 * inv;
}

__global__ __launch_bounds__(256)
void weno_kernel(const float* __restrict__ uu, float* __restrict__ out)
{
    int i = blockIdx.x * 256 + threadIdx.x;

    float um2 = uu[(i - 2) & MASK];
    float um1 = uu[(i - 1) & MASK];
    float u0  = uu[i];
    float up1 = uu[(i + 1) & MASK];
    float up2 = uu[(i + 2) & MASK];
    float up3 = uu[(i + 3) & MASK];

    float bmm = g_bm[(i - 1) & MASK];
    float bm0 = g_bm[i];
    float bmp = g_bm[(i + 1) & MASK];

    const float c16 = 1.0f / 6.0f;
    const float c1312 = 13.0f / 12.0f;

    float fn0 = (11.0f * u0 - 7.0f * up1 + 2.0f * up2) * c16;
    float fn1 = (2.0f * um1 + 5.0f * u0 - up1) * c16;
    float fn2 = (-um2 + 5.0f * um1 + 2.0f * u0) * c16;
    float fp0 = (11.0f * up1 - 7.0f * up2 + 2.0f * up3) * c16;
    float fp1 = (2.0f * u0 + 5.0f * up1 - up2) * c16;
    float fp2 = (-um1 + 5.0f * u0 + 2.0f * up1) * c16;

    float t;
    t = u0 - 2.0f * up1 + up2;
    float bn0 = c1312 * t * t;
    t = 3.0f * u0 - 4.0f * up1 + up2;
    bn0 += 0.25f * t * t;
    t = um1 - 2.0f * u0 + up1;
    float bn1 = c1312 * t * t;
    t = um1 - up1;
    bn1 += 0.25f * t * t;
    t = um2 - 2.0f * um1 + u0;
    float bn2 = c1312 * t * t;
    t = um2 - 4.0f * um1 + 3.0f * u0;
    bn2 += 0.25f * t * t;

    t = up1 - 2.0f * up2 + up3;
    float bp0 = c1312 * t * t;
    t = 3.0f * up1 - 4.0f * up2 + up3;
    bp0 += 0.25f * t * t;
    t = u0 - 2.0f * up1 + up2;
    float bp1 = c1312 * t * t;
    t = u0 - up2;
    bp1 += 0.25f * t * t;
    t = um1 - 2.0f * u0 + up1;
    float bp2 = c1312 * t * t;
    t = um1 - 4.0f * u0 + 3.0f * up1;
    bp2 += 0.25f * t * t;

    bn0 *= bmp; bn1 *= bm0; bn2 *= bmm;
    bp0 *= bmp; bp1 *= bm0; bp2 *= bmm;

    float on0, on1, on2, op0, op1, op2;
    omegas3(bn0, bn1, bn2, on0, on1, on2);
    omegas3(bp0, bp1, bp2, op0, op1, op2);

    float fluxp = op0 * fp0 + op1 * fp1 + op2 * fp2;
    float fluxn = on0 * fn0 + on1 * fn1 + on2 * fn2;
    out[i] = fluxp - fluxn;
}

// =====================================================================
extern "C" void kernel_launch(void* const* d_in, const int* in_sizes, int n_in,
                              void* d_out, int out_size)
{
    (void)in_sizes; (void)n_in; (void)out_size;
    const float* uu = (const float*)d_in[0];
    const float* w1 = (const float*)d_in[1];  const float* b1 = (const float*)d_in[2];
    const float* w2 = (const float*)d_in[3];  const float* b2 = (const float*)d_in[4];
    const float* w3 = (const float*)d_in[5];  const float* b3 = (const float*)d_in[6];
    const float* w4 = (const float*)d_in[7];  const float* b4 = (const float*)d_in[8];
    const float* w5 = (const float*)d_in[9];  const float* b5 = (const float*)d_in[10];
    const float* w6 = (const float*)d_in[11]; const float* b6 = (const float*)d_in[12];

    cudaFuncSetAttribute(cnn_kernel,
                         cudaFuncAttributeMaxDynamicSharedMemorySize, SMEM_BYTES);

    cnn_kernel<<<N_TOT / TILE, NT, SMEM_BYTES>>>(uu, w1, b1, w2, b2, w3, b3,
                                                 w4, b4, w5, b5, w6, b6);
    weno_kernel<<<N_TOT / 256, 256>>>(uu, (float*)d_out);
}